// round 2
// baseline (speedup 1.0000x reference)
#include <cuda_runtime.h>
#include <cstdint>

// Problem constants (fixed by the reference)
#define GW 64
#define GL 64
#define GH 64
#define GV (GW * GL * GH)          // 262144 voxels
#define INV_VOXEL 20.0f            // f32-rounded 1/0.05 (matches XLA's x*(1/c) rewrite)
#define MIN_PTS 10

// Scratch: per-(batch,voxel) in-bounds point counts. Sized for B=4.
__device__ int g_counts[4 * GV];

// ---------------------------------------------------------------------------
// Kernel 1: init voxeldata to -inf and counts to 0 (every launch, so the
// captured graph is replay-deterministic).
// ---------------------------------------------------------------------------
__global__ void init_kernel(uint4* __restrict__ data, long ndata4,
                            uint4* __restrict__ counts, long ncnt4) {
    long i = (long)blockIdx.x * blockDim.x + threadIdx.x;
    const uint4 ninf = make_uint4(0xFF800000u, 0xFF800000u, 0xFF800000u, 0xFF800000u);
    if (i < ndata4) data[i] = ninf;
    if (i < ncnt4)  counts[i] = make_uint4(0u, 0u, 0u, 0u);
}

// float atomic max via signed/unsigned int atomics (works for all finite
// floats and the -inf init value; NaNs absent in this workload)
__device__ __forceinline__ void atomicMaxFloat(float* addr, float value) {
    if (value >= 0.0f) {
        atomicMax((int*)addr, __float_as_int(value));
    } else {
        atomicMin((unsigned int*)addr, __float_as_uint(value));
    }
}

// ---------------------------------------------------------------------------
// Kernel 2: per-point scatter. coords [B,3,N], attrs [B,C,N],
// out voxeldata region [B,C,V] (V = W*L*H, flat = x*L*H + y*H + z)
// ---------------------------------------------------------------------------
__global__ void scatter_kernel(const float* __restrict__ coords,
                               const float* __restrict__ attrs,
                               float* __restrict__ out,
                               int B, int C, int N) {
    int i = blockIdx.x * blockDim.x + threadIdx.x;
    int total = B * N;
    if (i >= total) return;
    int b = i / N;
    int n = i - b * N;

    const float* cb = coords + (size_t)b * 3 * N;
    float px = __ldg(cb + n);
    float py = __ldg(cb + N + n);
    float pz = __ldg(cb + 2 * N + n);

    // Bit-match the reference: floor(p * 20.0f + 0.5f) with separate RN ops
    // (intrinsics prevent FMA contraction, which would change rounding)
    int cx = (int)floorf(__fadd_rn(__fmul_rn(px, INV_VOXEL), 0.5f));
    int cy = (int)floorf(__fadd_rn(__fmul_rn(py, INV_VOXEL), 0.5f));
    int cz = (int)floorf(__fadd_rn(__fmul_rn(pz, INV_VOXEL), 0.5f));

    if ((unsigned)cx >= (unsigned)GW ||
        (unsigned)cy >= (unsigned)GL ||
        (unsigned)cz >= (unsigned)GH) return;

    int flat = (cx * GL + cy) * GH + cz;

    atomicAdd(&g_counts[b * GV + flat], 1);

    const float* ab = attrs + ((size_t)b * C) * N + n;
    float*       ob = out   + ((size_t)b * C) * GV + flat;

    #pragma unroll 8
    for (int c = 0; c < C; c++) {
        float v = __ldg(ab + (size_t)c * N);
        atomicMaxFloat(ob + (size_t)c * GV, v);
    }
}

// ---------------------------------------------------------------------------
// Kernel 3: finalize. Write occupancy; zero channels of empty voxels.
// ---------------------------------------------------------------------------
__global__ void finalize_kernel(float* __restrict__ out,
                                float* __restrict__ occ,
                                int B, int C) {
    int i = blockIdx.x * blockDim.x + threadIdx.x;
    if (i >= B * GV) return;
    int b = i / GV;
    int flat = i - b * GV;
    int cnt = g_counts[i];
    occ[i] = (cnt >= MIN_PTS) ? 1.0f : 0.0f;
    if (cnt == 0) {
        float* ob = out + ((size_t)b * C) * GV + flat;
        #pragma unroll 8
        for (int c = 0; c < C; c++) {
            ob[(size_t)c * GV] = 0.0f;
        }
    }
}

// ---------------------------------------------------------------------------
extern "C" void kernel_launch(void* const* d_in, const int* in_sizes, int n_in,
                              void* d_out, int out_size) {
    const float* coords = (const float*)d_in[0];  // [B,3,N]
    const float* attrs  = (const float*)d_in[1];  // [B,C,N]
    float* out = (float*)d_out;                   // [B,C,V] then [B,1,V]

    // Derive shapes: in_sizes[0]=B*3*N, in_sizes[1]=B*C*N, out=B*(C+1)*V
    int C = (int)((3LL * in_sizes[1]) / in_sizes[0]);
    int B = (int)(out_size / ((long)(C + 1) * GV));
    int N = in_sizes[0] / (3 * B);

    float* occ = out + (size_t)B * C * GV;

    int* counts_dev = nullptr;
    cudaGetSymbolAddress((void**)&counts_dev, g_counts);

    long ndata4 = ((long)B * C * GV) / 4;
    long ncnt4  = ((long)B * GV) / 4;
    long nmax   = ndata4 > ncnt4 ? ndata4 : ncnt4;
    {
        int threads = 256;
        long blocks = (nmax + threads - 1) / threads;
        init_kernel<<<(unsigned)blocks, threads>>>((uint4*)out, ndata4,
                                                   (uint4*)counts_dev, ncnt4);
    }
    {
        int threads = 256;
        int total = B * N;
        int blocks = (total + threads - 1) / threads;
        scatter_kernel<<<blocks, threads>>>(coords, attrs, out, B, C, N);
    }
    {
        int threads = 256;
        int total = B * GV;
        int blocks = (total + threads - 1) / threads;
        finalize_kernel<<<blocks, threads>>>(out, occ, B, C);
    }
}